// round 11
// baseline (speedup 1.0000x reference)
#include <cuda_runtime.h>
#include <cuda_bf16.h>
#include <stdint.h>

#define GN 512
#define GW 332
#define GH 324
#define GHW (GW * GH)
#define GC 120
#define TSX 16
#define TSY 4
#define CUT 25.0f      // 5-sigma: exp(-12.5) ~ 3.7e-6

static __device__ __forceinline__ unsigned order_float(float f) {
    unsigned u = __float_as_uint(f);
    return (u & 0x80000000u) ? ~u : (u | 0x80000000u);
}

// Packed f32x2 helpers (Blackwell dual-fp32 pipe; FFMA2 only via PTX).
static __device__ __forceinline__ unsigned long long pack2(float lo, float hi) {
    unsigned long long r;
    asm("mov.b64 %0, {%1, %2};" : "=l"(r) : "f"(lo), "f"(hi));
    return r;
}
static __device__ __forceinline__ void unpack2(unsigned long long v, float& lo, float& hi) {
    asm("mov.b64 {%0, %1}, %2;" : "=f"(lo), "=f"(hi) : "l"(v));
}
static __device__ __forceinline__ unsigned long long fma2(
    unsigned long long a, unsigned long long b, unsigned long long c) {
    unsigned long long d;
    asm("fma.rn.f32x2 %0, %1, %2, %3;" : "=l"(d) : "l"(a), "l"(b), "l"(c));
    return d;
}

// ---------------------------------------------------------------------------
// Single fused kernel. Block = 256 threads = 64 pixels (16x4 tile) x 4
// channel groups. Each block:
//   1) projects all 512 gaussians (2 per thread, index order preserved)
//   2) ballot-compacts those whose 5-sigma ellipse reaches the tile
//   3) bitonic-sorts the culled list by (depth, slot)  == stable argsort
//   4) permutes params into depth order in smem
//   5) depth-ordered alpha compositing; spectral accumulation uses packed
//      fma.rn.f32x2 (FFMA2) -> half the FMA issue count
// ---------------------------------------------------------------------------
__global__ __launch_bounds__(256, 3) void fused_kernel(
    const float* __restrict__ pos,     // [N,3]
    const float* __restrict__ scales,  // [N,3]
    const float* __restrict__ ops,     // [N]
    const float* __restrict__ spec,    // [N,C]
    const float* __restrict__ tone,    // [C]
    const float* __restrict__ K,       // [3,3]
    const float* __restrict__ E,       // [4,4]
    float* __restrict__ out)           // [C*HW + HW + HW]
{
    __shared__ float4 a1[GN], a2[GN];           // staged (index order)
    __shared__ float4 b1[GN], b2[GN];           // depth-sorted
    __shared__ unsigned long long s_key[GN];
    __shared__ float s_tone[GC];
    __shared__ int   s_cnt, s_wcnt[8];

    const int tid = threadIdx.x;
    if (tid < GC) s_tone[tid] = __ldg(tone + tid);
    if (tid == 0) s_cnt = 0;

    const int x0 = blockIdx.x * TSX, y0 = blockIdx.y * TSY;
    const float fx0 = (float)x0, fx1 = (float)(x0 + TSX - 1);
    const float fy0 = (float)y0, fy1 = (float)(y0 + TSY - 1);

    // Camera matrices (uniform broadcast loads, L1/L2 cached).
    float E0 = __ldg(E + 0), E1 = __ldg(E + 1), E2  = __ldg(E + 2),  E3  = __ldg(E + 3);
    float E4 = __ldg(E + 4), E5 = __ldg(E + 5), E6  = __ldg(E + 6),  E7  = __ldg(E + 7);
    float E8 = __ldg(E + 8), E9 = __ldg(E + 9), E10 = __ldg(E + 10), E11 = __ldg(E + 11);
    float K0 = __ldg(K + 0), K1 = __ldg(K + 1), K2 = __ldg(K + 2);
    float K3 = __ldg(K + 3), K4 = __ldg(K + 4), K5 = __ldg(K + 5);
    float K6 = __ldg(K + 6), K7 = __ldg(K + 7), K8 = __ldg(K + 8);
    __syncthreads();

    // ---- Project + ellipse cull, 2 chunks of 256 (index order preserved) ----
#pragma unroll
    for (int c = 0; c < 2; c++) {
        const int i = c * 256 + tid;
        float p0 = __ldg(pos + 3 * i + 0), p1 = __ldg(pos + 3 * i + 1), p2 = __ldg(pos + 3 * i + 2);
        float cx = E0 * p0 + E1 * p1 + E2  * p2 + E3;
        float cy = E4 * p0 + E5 * p1 + E6  * p2 + E7;
        float cz = E8 * p0 + E9 * p1 + E10 * p2 + E11;
        float prx = K0 * cx + K1 * cy + K2 * cz;
        float pry = K3 * cx + K4 * cy + K5 * cz;
        float prz = K6 * cx + K7 * cy + K8 * cz;
        float sx = prx / (prz + 1e-6f);
        float sy = pry / (prz + 1e-6f);
        float d  = cz;

        bool valid = (d > 0.01f) && (d < 100.0f) &&
                     (sx > -100.0f) && (sx < (float)GW + 100.0f) &&
                     (sy > -100.0f) && (sy < (float)GH + 100.0f);

        float s0 = __ldg(scales + 3 * i + 0), s1v = __ldg(scales + 3 * i + 1);
        float c00 = 1.0f / (s0 * s0 + 1e-4f);
        float c11 = 1.0f / (s1v * s1v + 1e-4f);

        // Exact min mahalanobis over the tile rect: clamp center to rect.
        float nx = fminf(fmaxf(sx, fx0), fx1);
        float ny = fminf(fmaxf(sy, fy0), fy1);
        float ddx = sx - nx, ddy = sy - ny;
        float m_min = ddx * ddx * c00 + ddy * ddy * c11;

        bool keep = valid && (m_min < CUT);

        unsigned bm = __ballot_sync(0xffffffffu, keep);
        int lane = tid & 31, w = tid >> 5;
        if (lane == 0) s_wcnt[w] = __popc(bm);
        __syncthreads();
        int woff = 0;
#pragma unroll
        for (int ww = 0; ww < 8; ww++)
            if (ww < w) woff += s_wcnt[ww];
        if (keep) {
            int p = s_cnt + woff + __popc(bm & ((1u << lane) - 1u));
            a1[p] = make_float4(sx, sy, c00, c11);
            a2[p] = make_float4(__ldg(ops + i), d, __int_as_float(i), 0.0f);
            s_key[p] = ((unsigned long long)order_float(d) << 32) | (unsigned)p;
        }
        __syncthreads();
        if (tid == 0) {
            int tt = 0;
#pragma unroll
            for (int ww = 0; ww < 8; ww++) tt += s_wcnt[ww];
            s_cnt += tt;
        }
        __syncthreads();
    }
    const int cnt = s_cnt;

    // ---- Local bitonic sort by (depth, slot) ----
    int p2 = 1;
    while (p2 < cnt) p2 <<= 1;
    for (int p = cnt + tid; p < p2; p += 256)
        s_key[p] = 0xffffffffffffffffull;
    __syncthreads();
    for (int k = 2; k <= p2; k <<= 1) {
        for (int j = k >> 1; j > 0; j >>= 1) {
            if (tid < (p2 >> 1)) {
                int i = ((tid & ~(j - 1)) << 1) | (tid & (j - 1));
                int ixj = i | j;
                unsigned long long va = s_key[i], vb = s_key[ixj];
                bool asc = ((i & k) == 0);
                if ((va > vb) == asc) { s_key[i] = vb; s_key[ixj] = va; }
            }
            __syncthreads();
        }
    }

    // ---- Permute into depth order ----
    for (int p = tid; p < cnt; p += 256) {
        int slot = (int)(s_key[p] & 0xffffffffu);
        b1[p] = a1[slot];
        b2[p] = a2[slot];
    }
    __syncthreads();

    // ---- Compositing ----
    const int cg  = tid >> 6;          // channel group 0..3 (warp-uniform)
    const int pix = tid & 63;          // pixel within 16x4 tile
    const int px  = x0 + (pix & 15);
    const int py  = y0 + (pix >> 4);
    const float fpx = (float)px, fpy = (float)py;
    const int cbase = cg * 32;         // 0,32,64,96

    float A = 0.0f, D = 0.0f;
    unsigned long long acc2[16];       // 32 channels as 16 packed f32x2
#pragma unroll
    for (int c = 0; c < 16; c++) acc2[c] = 0ull;

    for (int k = 0; k < cnt; k++) {
        float4 P1 = b1[k];
        float4 P2 = b2[k];
        float dx = fpx - P1.x;
        float dy = fpy - P1.y;
        float m  = dx * dx * P1.z + dy * dy * P1.w;
        float alpha = P2.x * __expf(-0.5f * m) * (1.0f - A);
        A += alpha;
        D += P2.y * alpha;
        // Skip the spectral FMA block if every lane's alpha is negligible.
        if (!__any_sync(0xffffffffu, alpha > 1e-7f)) continue;
        unsigned long long alpha2 = pack2(alpha, alpha);
        const ulonglong2* sp = (const ulonglong2*)(spec + (size_t)__float_as_int(P2.z) * GC + cbase);
        if (cg < 3) {
#pragma unroll
            for (int q = 0; q < 8; q++) {
                ulonglong2 v = __ldg(sp + q);
                acc2[2 * q + 0] = fma2(v.x, alpha2, acc2[2 * q + 0]);
                acc2[2 * q + 1] = fma2(v.y, alpha2, acc2[2 * q + 1]);
            }
        } else {
#pragma unroll
            for (int q = 0; q < 6; q++) {
                ulonglong2 v = __ldg(sp + q);
                acc2[2 * q + 0] = fma2(v.x, alpha2, acc2[2 * q + 0]);
                acc2[2 * q + 1] = fma2(v.y, alpha2, acc2[2 * q + 1]);
            }
        }
    }

    if (px < GW) {   // py always < GH (324 = 81*4)
        const int p = py * GW + px;
        const float bg = 1.0f - A;   // BG = 1.0
        const int npair = (cg < 3) ? 16 : 12;
#pragma unroll 8
        for (int j = 0; j < npair; j++) {
            float lo, hi;
            unpack2(acc2[j], lo, hi);
            out[(size_t)(cbase + 2 * j + 0) * GHW + p] = (lo + bg) * s_tone[cbase + 2 * j + 0];
            out[(size_t)(cbase + 2 * j + 1) * GHW + p] = (hi + bg) * s_tone[cbase + 2 * j + 1];
        }
        if (cg == 0) {
            out[(size_t)GC * GHW + p] = D;              // depth image
            out[(size_t)GC * GHW + GHW + p] = A;        // A_final
        }
    }
}

// ---------------------------------------------------------------------------
// Inputs (metadata order): positions[N,3], rotations[N,4](unused), scales[N,3],
// opacities[N], spectral_features[N,C], tone_mapping[C], intrinsics[3,3],
// extrinsics[4,4]. Output: concat(spectral[C,H,W], depth[H,W], A[H,W]) fp32.
// ---------------------------------------------------------------------------
extern "C" void kernel_launch(void* const* d_in, const int* in_sizes, int n_in,
                              void* d_out, int out_size)
{
    const float* positions  = (const float*)d_in[0];
    const float* scales     = (const float*)d_in[2];
    const float* opacities  = (const float*)d_in[3];
    const float* spectral   = (const float*)d_in[4];
    const float* tone       = (const float*)d_in[5];
    const float* intr       = (const float*)d_in[6];
    const float* extr       = (const float*)d_in[7];
    float* out = (float*)d_out;

    dim3 grid((GW + TSX - 1) / TSX, (GH + TSY - 1) / TSY);
    fused_kernel<<<grid, 256>>>(positions, scales, opacities, spectral, tone,
                                intr, extr, out);
}